// round 15
// baseline (speedup 1.0000x reference)
#include <cuda_runtime.h>
#include <cstdint>

#define BATCH    128
#define N0       25600   // 160x160
#define N1       6400    // 80x80
#define N2       1600    // 40x40
#define NTOT     33600
#define KTOP     1000
#define THREADS  1024
#define REG_ROWS 14                 // per-thread candidate cap
#define CAND_CAP 4096
#define THR_F    1.8f               // conservative cutoff; exact fallback otherwise

typedef unsigned long long u64;
typedef unsigned int u32;

struct Smem {
    u64 cand[CAND_CAP];             // 32768 B
    u64 region[REG_ROWS * THREADS]; // 114688 B  [row][tid] thread-private slots
    u32 hist[2048];                 // 8192 B (fallback only)
    u32 wtot[32];
    u32 wexcl[32];
    u32 wover[32];
    u32 wsum[32];
    u32 wexcl2[32];
    int mtotal;
    int overflow;
    int tbin;
    int ccount;
};

__device__ __forceinline__ u32 make_key(u32 u) {
    return u ^ (((u32)((int)u >> 31)) | 0x80000000u);
}

// warp CE via shfl.xor; element bit-j parity given by lane&j (valid for j<=16)
__device__ __forceinline__ u64 ce_shfl(u64 v, int j, bool desc, int lane) {
    u64 p = __shfl_xor_sync(0xffffffffu, v, j);
    bool keepmax = (((lane & j) == 0) == desc);
    u64 mx = v > p ? v : p;
    u64 mn = v > p ? p : v;
    return keepmax ? mx : mn;
}

// Predicated shared store: single @p STS.64, no branch, no BSSY.
__device__ __forceinline__ void pred_sts64(u32 doit, u64* p, u64 val) {
    u32 saddr = (u32)__cvta_generic_to_shared(p);
    asm volatile("{\n\t"
                 ".reg .pred p;\n\t"
                 "setp.ne.u32 p, %0, 0;\n\t"
                 "@p st.shared.b64 [%1], %2;\n\t"
                 "}"
                 :: "r"(doit), "r"(saddr), "l"(val) : "memory");
}

__device__ __forceinline__ int proc1(u64* region, float x, bool vk, u32 gidx,
                                     int tid, int cnt) {
    bool pred = vk && (x > THR_F);
    int row = (cnt < REG_ROWS) ? cnt : (REG_ROWS - 1);
    u64 val = ((u64)__float_as_uint(x) << 32) | (u32)(~gidx);
    pred_sts64(pred ? 1u : 0u, &region[row * THREADS + tid], val);
    return cnt + (pred ? 1 : 0);
}

__device__ __forceinline__ int proc4(u64* region, float4 f, bool vk, u32 gi,
                                     int tid, int cnt) {
    cnt = proc1(region, f.x, vk, gi + 0, tid, cnt);
    cnt = proc1(region, f.y, vk, gi + 1, tid, cnt);
    cnt = proc1(region, f.z, vk, gi + 2, tid, cnt);
    cnt = proc1(region, f.w, vk, gi + 3, tid, cnt);
    return cnt;
}

// L2-prefetch the 4 bbox values of one candidate (overlaps with the sort).
__device__ __forceinline__ void prefetch_bbox(int b, u64 e,
                                              const float* bb0,
                                              const float* bb1,
                                              const float* bb2) {
    u32 idx = ~(u32)(e & 0xFFFFFFFFull);
    int jj, hw;
    const float* bp;
    if (idx < N0)           { jj = (int)idx;            hw = N0; bp = bb0 + (size_t)b * 4 * N0; }
    else if (idx < N0 + N1) { jj = (int)idx - N0;       hw = N1; bp = bb1 + (size_t)b * 4 * N1; }
    else                    { jj = (int)idx - N0 - N1;  hw = N2; bp = bb2 + (size_t)b * 4 * N2; }
    asm volatile("prefetch.global.L2 [%0];" :: "l"(bp + jj));
    asm volatile("prefetch.global.L2 [%0];" :: "l"(bp + hw + jj));
    asm volatile("prefetch.global.L2 [%0];" :: "l"(bp + 2 * hw + jj));
    asm volatile("prefetch.global.L2 [%0];" :: "l"(bp + 3 * hw + jj));
}

// Decode + write one output row.
__device__ __forceinline__ void emit_row(int b, int rank, u64 e,
                                         const float* bb0, const float* bb1,
                                         const float* bb2,
                                         float* out_boxes, float* out_scores) {
    u32 key = (u32)(e >> 32);
    u32 idx = ~(u32)(e & 0xFFFFFFFFull);

    float logit = (key & 0x80000000u)
                ? __uint_as_float(key ^ 0x80000000u)
                : __uint_as_float(~key);
    float sc = 1.0f / (1.0f + __expf(-logit));
    out_scores[(size_t)b * KTOP + rank] = sc;

    int jj, sh, hw;
    const float* bp;
    if (idx < N0)           { jj = (int)idx;            sh = 5; hw = N0; bp = bb0 + (size_t)b * 4 * N0; }
    else if (idx < N0 + N1) { jj = (int)idx - N0;       sh = 4; hw = N1; bp = bb1 + (size_t)b * 4 * N1; }
    else                    { jj = (int)idx - N0 - N1;  sh = 3; hw = N2; bp = bb2 + (size_t)b * 4 * N2; }

    int st = 256 >> sh;                      // stride: 8/16/32
    int y  = (int)((u32)(jj >> sh) / 5u);    // w = 5<<sh
    int x  = jj - y * (5 << sh);
    float px = (float)(x * st);
    float py = (float)(y * st);

    float dl = bp[jj];
    float dt = bp[hw + jj];
    float dr = bp[2 * hw + jj];
    float db = bp[3 * hw + jj];

    float4 box = make_float4(px - dl, py - dt, px + dr, py + db);
    *reinterpret_cast<float4*>(&out_boxes[((size_t)b * KTOP + rank) * 4]) = box;
}

// ---------- exact fallback (never taken on in-distribution data) ----------
__device__ __forceinline__ void hist_pass(Smem& sm, const float* src, int n4, int tid) {
    const float4* v = reinterpret_cast<const float4*>(src);
    for (int i = tid; i < n4; i += THREADS) {
        float4 f = v[i];
        atomicAdd(&sm.hist[make_key(__float_as_uint(f.x)) >> 21], 1u);
        atomicAdd(&sm.hist[make_key(__float_as_uint(f.y)) >> 21], 1u);
        atomicAdd(&sm.hist[make_key(__float_as_uint(f.z)) >> 21], 1u);
        atomicAdd(&sm.hist[make_key(__float_as_uint(f.w)) >> 21], 1u);
    }
}

__device__ __forceinline__ void compact_bin(Smem& sm, const float* src, int n4,
                                            int base, u32 T, int tid, int lane) {
    const float4* v = reinterpret_cast<const float4*>(src);
    const int lim = ((n4 + THREADS - 1) / THREADS) * THREADS;
    for (int i = tid; i < lim; i += THREADS) {
        bool valid = i < n4;
        float4 f = make_float4(0, 0, 0, 0);
        if (valid) f = v[i];
        #pragma unroll
        for (int s = 0; s < 4; s++) {
            float x = (s == 0) ? f.x : (s == 1) ? f.y : (s == 2) ? f.z : f.w;
            u32 key = make_key(__float_as_uint(x));
            bool pred = valid && ((key >> 21) >= T);
            u32 m = __ballot_sync(0xffffffffu, pred);
            if (m) {
                int bsum = 0;
                if (lane == 0) bsum = atomicAdd(&sm.ccount, __popc(m));
                bsum = __shfl_sync(0xffffffffu, bsum, 0);
                if (pred) {
                    int p = bsum + __popc(m & ((1u << lane) - 1u));
                    if (p < CAND_CAP) {
                        u32 gidx = (u32)(base + 4 * i + s);
                        sm.cand[p] = ((u64)key << 32) | (u32)(~gidx);
                    }
                }
            }
        }
    }
}
// --------------------------------------------------------------------------

__global__ __launch_bounds__(THREADS, 1)
void topk_decode_kernel(const float* __restrict__ cls0,
                        const float* __restrict__ cls1,
                        const float* __restrict__ cls2,
                        const float* __restrict__ bb0,
                        const float* __restrict__ bb1,
                        const float* __restrict__ bb2,
                        float* __restrict__ out)
{
    extern __shared__ char smem_raw[];
    Smem& sm = *reinterpret_cast<Smem*>(smem_raw);
    const int b    = blockIdx.x;
    const int tid  = threadIdx.x;
    const int lane = tid & 31;
    const int wid  = tid >> 5;

    if (tid == 0) { sm.tbin = -1; sm.ccount = 0; }

    const float* c0 = cls0 + (size_t)b * N0;
    const float* c1 = cls1 + (size_t)b * N1;
    const float* c2 = cls2 + (size_t)b * N2;
    const float4* v0 = reinterpret_cast<const float4*>(c0);
    const float4* v1 = reinterpret_cast<const float4*>(c1);
    const float4* v2 = reinterpret_cast<const float4*>(c2);

    // ---- streaming in 2 chunks (lower register pressure, no spills) ----
    int cnt = 0;
    {   // chunk A: seg0 k=0..5, all fully valid (6143 < 6400)
        float4 bufA[6];
        #pragma unroll
        for (int k = 0; k < 6; k++) bufA[k] = v0[tid + k * THREADS];
        #pragma unroll
        for (int k = 0; k < 6; k++)
            cnt = proc4(sm.region, bufA[k], true,
                        (u32)(4 * (tid + k * THREADS)), tid, cnt);
    }
    {   // chunk B: seg0 k=6 (tid<256), seg1 k=0 (full), seg1 k=1 (tid<576),
        //          seg2 (tid<400)
        bool vB0 = tid < (N0 / 4 - 6 * THREADS);   // 256
        bool vB2 = tid < (N1 / 4 - THREADS);       // 576
        bool vB3 = tid < (N2 / 4);                 // 400
        float4 bufB[4];
        bufB[0] = v0[vB0 ? tid + 6 * THREADS : 0];
        bufB[1] = v1[tid];
        bufB[2] = v1[vB2 ? tid + THREADS : 0];
        bufB[3] = v2[vB3 ? tid : 0];
        cnt = proc4(sm.region, bufB[0], vB0, (u32)(4 * (tid + 6 * THREADS)), tid, cnt);
        cnt = proc4(sm.region, bufB[1], true, (u32)(N0 + 4 * tid), tid, cnt);
        cnt = proc4(sm.region, bufB[2], vB2, (u32)(N0 + 4 * (tid + THREADS)), tid, cnt);
        cnt = proc4(sm.region, bufB[3], vB3, (u32)(N0 + N1 + 4 * tid), tid, cnt);
    }

    // ---- block scan of per-thread counts ----
    u32 xv = (u32)cnt;
    #pragma unroll
    for (int off = 1; off < 32; off <<= 1) {
        u32 y = __shfl_up_sync(0xffffffffu, xv, off);
        if (lane >= off) xv += y;
    }
    if (lane == 31) sm.wtot[wid] = xv;
    u32 over = __ballot_sync(0xffffffffu, cnt > REG_ROWS);
    if (lane == 0) sm.wover[wid] = over;
    __syncthreads();
    if (tid < 32) {
        u32 t = sm.wtot[tid];
        u32 w = t;
        #pragma unroll
        for (int off = 1; off < 32; off <<= 1) {
            u32 y = __shfl_up_sync(0xffffffffu, w, off);
            if (tid >= off) w += y;
        }
        sm.wexcl[tid] = w - t;
        u32 ovb = __ballot_sync(0xffffffffu, sm.wover[tid] != 0u);
        if (tid == 31) sm.mtotal = (int)w;
        if (tid == 0)  sm.overflow = (ovb != 0u) ? 1 : 0;
    }
    __syncthreads();

    int M = sm.mtotal;
    bool bad = (sm.overflow != 0) || (M < KTOP) || (M > 2048);
    int P = 2048;

    if (!bad) {
        // dense compaction + L2 prefetch of bbox rows (overlaps the sort)
        int base = (int)(sm.wexcl[wid] + xv - (u32)cnt);
        for (int c = 0; c < cnt; c++) {
            u64 v = sm.region[c * THREADS + tid];
            sm.cand[base + c] = v | 0x8000000000000000ull;
            prefetch_bbox(b, v, bb0, bb1, bb2);
        }
        __syncthreads();
        for (int i = M + tid; i < 2048; i += THREADS) sm.cand[i] = 0ull;
        __syncthreads();
    } else {
        // ---- exact fallback: histogram select ----
        for (int i = tid; i < 2048; i += THREADS) sm.hist[i] = 0u;
        __syncthreads();
        hist_pass(sm, c0, N0 / 4, tid);
        hist_pass(sm, c1, N1 / 4, tid);
        hist_pass(sm, c2, N2 / 4, tid);
        __syncthreads();

        u32 h0 = sm.hist[2 * tid], h1 = sm.hist[2 * tid + 1];
        u32 s2 = h0 + h1;
        u32 v = s2;
        #pragma unroll
        for (int off = 1; off < 32; off <<= 1) {
            u32 u = __shfl_down_sync(0xffffffffu, v, off);
            if (lane + off < 32) v += u;
        }
        if (lane == 0) sm.wsum[wid] = v;
        __syncthreads();
        if (tid < 32) {
            u32 t = sm.wsum[tid];
            u32 w = t;
            #pragma unroll
            for (int off = 1; off < 32; off <<= 1) {
                u32 u = __shfl_down_sync(0xffffffffu, w, off);
                if (tid + off < 32) w += u;
            }
            sm.wexcl2[tid] = w - t;
        }
        __syncthreads();
        u32 gsuf  = v + sm.wexcl2[wid];
        u32 gnext = gsuf - s2;
        if (gsuf >= (u32)KTOP && gnext < (u32)KTOP)
            sm.tbin = (gnext + h1 >= (u32)KTOP) ? (2 * tid + 1) : (2 * tid);
        __syncthreads();

        u32 T = (u32)sm.tbin;
        compact_bin(sm, c0, N0 / 4, 0,       T, tid, lane);
        compact_bin(sm, c1, N1 / 4, N0,      T, tid, lane);
        compact_bin(sm, c2, N2 / 4, N0 + N1, T, tid, lane);
        __syncthreads();
        M = sm.ccount; if (M > CAND_CAP) M = CAND_CAP;
        P = (M <= 2048) ? 2048 : 4096;
        for (int i = M + tid; i < P; i += THREADS) sm.cand[i] = 0ull;
        __syncthreads();
    }

    float* out_boxes  = out;                            // [B, K, 4]
    float* out_scores = out + (size_t)BATCH * KTOP * 4; // [B, K, 1]

    if (P == 2048) {
        // ---- bitonic sort P=2048 desc, thread holds (e0, e0+32);
        //      j<=16 shfl, j==32 register, j>=64 smem branch-free CE ----
        const int e0 = (wid << 6) | lane;
        u64 a  = sm.cand[e0];
        u64 bb = sm.cand[e0 + 32];

        #pragma unroll
        for (int k = 2; k <= 32; k <<= 1) {
            bool dA = ((lane & k) == 0);
            bool dB = (((lane + 32) & k) == 0);
            #pragma unroll
            for (int j = k >> 1; j >= 1; j >>= 1) {
                a  = ce_shfl(a,  j, dA, lane);
                bb = ce_shfl(bb, j, dB, lane);
            }
        }
        {   // k = 64: register + shfl only
            bool dk = ((wid & 1) == 0);
            bool sw = dk ? (a < bb) : (a > bb);
            u64 t0 = sw ? bb : a, t1 = sw ? a : bb;
            a = t0; bb = t1;
            #pragma unroll
            for (int j = 16; j >= 1; j >>= 1) {
                a  = ce_shfl(a,  j, dk, lane);
                bb = ce_shfl(bb, j, dk, lane);
            }
        }
        for (int k = 128; k <= 2048; k <<= 1) {
            sm.cand[e0]      = a;
            sm.cand[e0 + 32] = bb;
            __syncthreads();
            for (int j = k >> 1; j >= 64; j >>= 1) {
                int i   = ((tid & ~(j - 1)) << 1) | (tid & (j - 1));
                int ixj = i | j;
                bool desc = ((i & k) == 0);
                u64 x = sm.cand[i];
                u64 y = sm.cand[ixj];
                u64 mx = x > y ? x : y;
                u64 mn = x > y ? y : x;
                sm.cand[i]   = desc ? mx : mn;
                sm.cand[ixj] = desc ? mn : mx;
                __syncthreads();
            }
            a  = sm.cand[e0];
            bb = sm.cand[e0 + 32];
            bool dk = ((e0 & k) == 0);
            bool sw = dk ? (a < bb) : (a > bb);
            u64 t0 = sw ? bb : a, t1 = sw ? a : bb;
            a = t0; bb = t1;
            #pragma unroll
            for (int j = 16; j >= 1; j >>= 1) {
                a  = ce_shfl(a,  j, dk, lane);
                bb = ce_shfl(bb, j, dk, lane);
            }
        }
        // thread holds rank e0 in `a`, rank e0+32 in `bb`: emit directly.
        if (e0 < KTOP)
            emit_row(b, e0, a, bb0, bb1, bb2, out_boxes, out_scores);
        if (e0 + 32 < KTOP)
            emit_row(b, e0 + 32, bb, bb0, bb1, bb2, out_boxes, out_scores);
    } else {
        // ---- generic smem bitonic, P=4096 (rare) ----
        for (int k = 2; k <= 4096; k <<= 1) {
            for (int j = k >> 1; j > 0; j >>= 1) {
                for (int i = tid; i < 4096; i += THREADS) {
                    int ixj = i ^ j;
                    if (ixj > i) {
                        u64 x = sm.cand[i];
                        u64 y = sm.cand[ixj];
                        bool desc = ((i & k) == 0);
                        if (desc ? (x < y) : (x > y)) {
                            sm.cand[i] = y;
                            sm.cand[ixj] = x;
                        }
                    }
                }
                __syncthreads();
            }
        }
        if (tid < KTOP)
            emit_row(b, tid, sm.cand[tid], bb0, bb1, bb2, out_boxes, out_scores);
    }
}

extern "C" void kernel_launch(void* const* d_in, const int* in_sizes, int n_in,
                              void* d_out, int out_size)
{
    const float *cls0, *cls1, *cls2, *b0, *b1, *b2;

    const int S_CLS0 = BATCH * N0;      // 3276800
    const int S_BB0  = BATCH * 4 * N0;  // 13107200

    if (n_in >= 6 && in_sizes[0] == S_CLS0 && in_sizes[1] == S_BB0) {
        // dict-insertion order: cls0, bbox0, cls1, bbox1, cls2, bbox2
        cls0 = (const float*)d_in[0]; b0 = (const float*)d_in[1];
        cls1 = (const float*)d_in[2]; b1 = (const float*)d_in[3];
        cls2 = (const float*)d_in[4]; b2 = (const float*)d_in[5];
    } else if (n_in >= 6 && in_sizes[0] == S_BB0) {
        // alphabetical order: bbox0, bbox1, bbox2, cls0, cls1, cls2
        b0   = (const float*)d_in[0]; b1   = (const float*)d_in[1];
        b2   = (const float*)d_in[2]; cls0 = (const float*)d_in[3];
        cls1 = (const float*)d_in[4]; cls2 = (const float*)d_in[5];
    } else {
        // signature order: cls0, cls1, cls2, bbox0, bbox1, bbox2
        cls0 = (const float*)d_in[0]; cls1 = (const float*)d_in[1];
        cls2 = (const float*)d_in[2]; b0   = (const float*)d_in[3];
        b1   = (const float*)d_in[4]; b2   = (const float*)d_in[5];
    }
    (void)in_sizes; (void)out_size;

    cudaFuncSetAttribute(topk_decode_kernel,
                         cudaFuncAttributeMaxDynamicSharedMemorySize,
                         (int)sizeof(Smem));

    topk_decode_kernel<<<BATCH, THREADS, sizeof(Smem)>>>(
        cls0, cls1, cls2, b0, b1, b2, (float*)d_out);
}

// round 16
// speedup vs baseline: 1.0977x; 1.0977x over previous
#include <cuda_runtime.h>
#include <cstdint>

#define BATCH    128
#define N0       25600   // 160x160
#define N1       6400    // 80x80
#define N2       1600    // 40x40
#define NTOT     33600
#define KTOP     1000
#define THREADS  1024
#define REG_ROWS 14                 // per-thread candidate cap
#define CAND_CAP 4096
#define THR_F    1.8f               // conservative cutoff; exact fallback otherwise

typedef unsigned long long u64;
typedef unsigned int u32;

struct Smem {
    u64 cand[CAND_CAP];             // 32768 B
    u64 region[REG_ROWS * THREADS]; // 114688 B  [row][tid] thread-private slots
    u32 hist[2048];                 // 8192 B (fallback only)
    u32 wtot[32];
    u32 wexcl[32];
    u32 wover[32];
    u32 wsum[32];
    u32 wexcl2[32];
    int mtotal;
    int overflow;
    int tbin;
    int ccount;
};

__device__ __forceinline__ u32 make_key(u32 u) {
    return u ^ (((u32)((int)u >> 31)) | 0x80000000u);
}

// warp CE via shfl.xor; element bit-j parity given by lane&j (valid for j<=16)
__device__ __forceinline__ u64 ce_shfl(u64 v, int j, bool desc, int lane) {
    u64 p = __shfl_xor_sync(0xffffffffu, v, j);
    bool keepmax = (((lane & j) == 0) == desc);
    u64 mx = v > p ? v : p;
    u64 mn = v > p ? p : v;
    return keepmax ? mx : mn;
}

// Predicated shared store: single @p STS.64, no branch, no BSSY.
__device__ __forceinline__ void pred_sts64(u32 doit, u64* p, u64 val) {
    u32 saddr = (u32)__cvta_generic_to_shared(p);
    asm volatile("{\n\t"
                 ".reg .pred p;\n\t"
                 "setp.ne.u32 p, %0, 0;\n\t"
                 "@p st.shared.b64 [%1], %2;\n\t"
                 "}"
                 :: "r"(doit), "r"(saddr), "l"(val) : "memory");
}

__device__ __forceinline__ int proc1(u64* region, float x, bool vk, u32 gidx,
                                     int tid, int cnt) {
    bool pred = vk && (x > THR_F);
    int row = (cnt < REG_ROWS) ? cnt : (REG_ROWS - 1);
    u64 val = ((u64)__float_as_uint(x) << 32) | (u32)(~gidx);
    pred_sts64(pred ? 1u : 0u, &region[row * THREADS + tid], val);
    return cnt + (pred ? 1 : 0);
}

__device__ __forceinline__ int proc4(u64* region, float4 f, bool vk, u32 gi,
                                     int tid, int cnt) {
    cnt = proc1(region, f.x, vk, gi + 0, tid, cnt);
    cnt = proc1(region, f.y, vk, gi + 1, tid, cnt);
    cnt = proc1(region, f.z, vk, gi + 2, tid, cnt);
    cnt = proc1(region, f.w, vk, gi + 3, tid, cnt);
    return cnt;
}

// Decode + write one output row.
__device__ __forceinline__ void emit_row(int b, int rank, u64 e,
                                         const float* bb0, const float* bb1,
                                         const float* bb2,
                                         float* out_boxes, float* out_scores) {
    u32 key = (u32)(e >> 32);
    u32 idx = ~(u32)(e & 0xFFFFFFFFull);

    float logit = (key & 0x80000000u)
                ? __uint_as_float(key ^ 0x80000000u)
                : __uint_as_float(~key);
    float sc = 1.0f / (1.0f + __expf(-logit));
    out_scores[(size_t)b * KTOP + rank] = sc;

    int jj, sh, hw;
    const float* bp;
    if (idx < N0)           { jj = (int)idx;            sh = 5; hw = N0; bp = bb0 + (size_t)b * 4 * N0; }
    else if (idx < N0 + N1) { jj = (int)idx - N0;       sh = 4; hw = N1; bp = bb1 + (size_t)b * 4 * N1; }
    else                    { jj = (int)idx - N0 - N1;  sh = 3; hw = N2; bp = bb2 + (size_t)b * 4 * N2; }

    int st = 256 >> sh;                      // stride: 8/16/32
    int y  = (int)((u32)(jj >> sh) / 5u);    // w = 5<<sh
    int x  = jj - y * (5 << sh);
    float px = (float)(x * st);
    float py = (float)(y * st);

    float dl = bp[jj];
    float dt = bp[hw + jj];
    float dr = bp[2 * hw + jj];
    float db = bp[3 * hw + jj];

    float4 box = make_float4(px - dl, py - dt, px + dr, py + db);
    *reinterpret_cast<float4*>(&out_boxes[((size_t)b * KTOP + rank) * 4]) = box;
}

// ---------- exact fallback (never taken on in-distribution data) ----------
__device__ __forceinline__ void hist_pass(Smem& sm, const float* src, int n4, int tid) {
    const float4* v = reinterpret_cast<const float4*>(src);
    for (int i = tid; i < n4; i += THREADS) {
        float4 f = v[i];
        atomicAdd(&sm.hist[make_key(__float_as_uint(f.x)) >> 21], 1u);
        atomicAdd(&sm.hist[make_key(__float_as_uint(f.y)) >> 21], 1u);
        atomicAdd(&sm.hist[make_key(__float_as_uint(f.z)) >> 21], 1u);
        atomicAdd(&sm.hist[make_key(__float_as_uint(f.w)) >> 21], 1u);
    }
}

__device__ __forceinline__ void compact_bin(Smem& sm, const float* src, int n4,
                                            int base, u32 T, int tid, int lane) {
    const float4* v = reinterpret_cast<const float4*>(src);
    const int lim = ((n4 + THREADS - 1) / THREADS) * THREADS;
    for (int i = tid; i < lim; i += THREADS) {
        bool valid = i < n4;
        float4 f = make_float4(0, 0, 0, 0);
        if (valid) f = v[i];
        #pragma unroll
        for (int s = 0; s < 4; s++) {
            float x = (s == 0) ? f.x : (s == 1) ? f.y : (s == 2) ? f.z : f.w;
            u32 key = make_key(__float_as_uint(x));
            bool pred = valid && ((key >> 21) >= T);
            u32 m = __ballot_sync(0xffffffffu, pred);
            if (m) {
                int bsum = 0;
                if (lane == 0) bsum = atomicAdd(&sm.ccount, __popc(m));
                bsum = __shfl_sync(0xffffffffu, bsum, 0);
                if (pred) {
                    int p = bsum + __popc(m & ((1u << lane) - 1u));
                    if (p < CAND_CAP) {
                        u32 gidx = (u32)(base + 4 * i + s);
                        sm.cand[p] = ((u64)key << 32) | (u32)(~gidx);
                    }
                }
            }
        }
    }
}
// --------------------------------------------------------------------------

__global__ __launch_bounds__(THREADS, 1)
void topk_decode_kernel(const float* __restrict__ cls0,
                        const float* __restrict__ cls1,
                        const float* __restrict__ cls2,
                        const float* __restrict__ bb0,
                        const float* __restrict__ bb1,
                        const float* __restrict__ bb2,
                        float* __restrict__ out)
{
    extern __shared__ char smem_raw[];
    Smem& sm = *reinterpret_cast<Smem*>(smem_raw);
    const int b    = blockIdx.x;
    const int tid  = threadIdx.x;
    const int lane = tid & 31;
    const int wid  = tid >> 5;

    if (tid == 0) { sm.tbin = -1; sm.ccount = 0; }

    const float* c0 = cls0 + (size_t)b * N0;
    const float* c1 = cls1 + (size_t)b * N1;
    const float* c2 = cls2 + (size_t)b * N2;
    const float4* v0 = reinterpret_cast<const float4*>(c0);
    const float4* v1 = reinterpret_cast<const float4*>(c1);
    const float4* v2 = reinterpret_cast<const float4*>(c2);

    // ---- streaming: preload ALL 10 float4s (single latency exposure) ----
    float4 buf[10];
    u32 vmask = 0;
    #pragma unroll
    for (int k = 0; k < 7; k++) {               // seg0: N0/4 = 6400
        int i = tid + k * THREADS;
        bool val = i < (N0 / 4);
        buf[k] = v0[val ? i : 0];
        vmask |= (val ? 1u : 0u) << k;
    }
    #pragma unroll
    for (int k = 0; k < 2; k++) {               // seg1: N1/4 = 1600
        int i = tid + k * THREADS;
        bool val = i < (N1 / 4);
        buf[7 + k] = v1[val ? i : 0];
        vmask |= (val ? 1u : 0u) << (7 + k);
    }
    {                                           // seg2: N2/4 = 400
        bool val = tid < (N2 / 4);
        buf[9] = v2[val ? tid : 0];
        vmask |= (val ? 1u : 0u) << 9;
    }

    int cnt = 0;
    #pragma unroll
    for (int k = 0; k < 7; k++)
        cnt = proc4(sm.region, buf[k], (vmask >> k) & 1u,
                    (u32)(4 * (tid + k * THREADS)), tid, cnt);
    #pragma unroll
    for (int k = 0; k < 2; k++)
        cnt = proc4(sm.region, buf[7 + k], (vmask >> (7 + k)) & 1u,
                    (u32)(N0 + 4 * (tid + k * THREADS)), tid, cnt);
    cnt = proc4(sm.region, buf[9], (vmask >> 9) & 1u,
                (u32)(N0 + N1 + 4 * tid), tid, cnt);

    // ---- block scan of per-thread counts ----
    u32 xv = (u32)cnt;
    #pragma unroll
    for (int off = 1; off < 32; off <<= 1) {
        u32 y = __shfl_up_sync(0xffffffffu, xv, off);
        if (lane >= off) xv += y;
    }
    if (lane == 31) sm.wtot[wid] = xv;
    u32 over = __ballot_sync(0xffffffffu, cnt > REG_ROWS);
    if (lane == 0) sm.wover[wid] = over;
    __syncthreads();
    if (tid < 32) {
        u32 t = sm.wtot[tid];
        u32 w = t;
        #pragma unroll
        for (int off = 1; off < 32; off <<= 1) {
            u32 y = __shfl_up_sync(0xffffffffu, w, off);
            if (tid >= off) w += y;
        }
        sm.wexcl[tid] = w - t;
        u32 ovb = __ballot_sync(0xffffffffu, sm.wover[tid] != 0u);
        if (tid == 31) sm.mtotal = (int)w;
        if (tid == 0)  sm.overflow = (ovb != 0u) ? 1 : 0;
    }
    __syncthreads();

    int M = sm.mtotal;
    bool bad = (sm.overflow != 0) || (M < KTOP) || (M > 2048);
    int P = 2048;

    if (!bad) {
        // dense compaction; positive floats -> order key == set MSB
        int base = (int)(sm.wexcl[wid] + xv - (u32)cnt);
        for (int c = 0; c < cnt; c++)
            sm.cand[base + c] = sm.region[c * THREADS + tid]
                              | 0x8000000000000000ull;
        __syncthreads();
        for (int i = M + tid; i < 2048; i += THREADS) sm.cand[i] = 0ull;
        __syncthreads();
    } else {
        // ---- exact fallback: histogram select ----
        for (int i = tid; i < 2048; i += THREADS) sm.hist[i] = 0u;
        __syncthreads();
        hist_pass(sm, c0, N0 / 4, tid);
        hist_pass(sm, c1, N1 / 4, tid);
        hist_pass(sm, c2, N2 / 4, tid);
        __syncthreads();

        u32 h0 = sm.hist[2 * tid], h1 = sm.hist[2 * tid + 1];
        u32 s2 = h0 + h1;
        u32 v = s2;
        #pragma unroll
        for (int off = 1; off < 32; off <<= 1) {
            u32 u = __shfl_down_sync(0xffffffffu, v, off);
            if (lane + off < 32) v += u;
        }
        if (lane == 0) sm.wsum[wid] = v;
        __syncthreads();
        if (tid < 32) {
            u32 t = sm.wsum[tid];
            u32 w = t;
            #pragma unroll
            for (int off = 1; off < 32; off <<= 1) {
                u32 u = __shfl_down_sync(0xffffffffu, w, off);
                if (tid + off < 32) w += u;
            }
            sm.wexcl2[tid] = w - t;
        }
        __syncthreads();
        u32 gsuf  = v + sm.wexcl2[wid];
        u32 gnext = gsuf - s2;
        if (gsuf >= (u32)KTOP && gnext < (u32)KTOP)
            sm.tbin = (gnext + h1 >= (u32)KTOP) ? (2 * tid + 1) : (2 * tid);
        __syncthreads();

        u32 T = (u32)sm.tbin;
        compact_bin(sm, c0, N0 / 4, 0,       T, tid, lane);
        compact_bin(sm, c1, N1 / 4, N0,      T, tid, lane);
        compact_bin(sm, c2, N2 / 4, N0 + N1, T, tid, lane);
        __syncthreads();
        M = sm.ccount; if (M > CAND_CAP) M = CAND_CAP;
        P = (M <= 2048) ? 2048 : 4096;
        for (int i = M + tid; i < P; i += THREADS) sm.cand[i] = 0ull;
        __syncthreads();
    }

    float* out_boxes  = out;                            // [B, K, 4]
    float* out_scores = out + (size_t)BATCH * KTOP * 4; // [B, K, 1]

    if (P == 2048) {
        // ---- bitonic sort P=2048 desc, thread holds (e0, e0+32);
        //      j<=16 shfl, j==32 register, j>=64 smem branch-free CE ----
        const int e0 = (wid << 6) | lane;
        u64 a  = sm.cand[e0];
        u64 bb = sm.cand[e0 + 32];

        #pragma unroll
        for (int k = 2; k <= 32; k <<= 1) {
            bool dA = ((lane & k) == 0);
            bool dB = (((lane + 32) & k) == 0);
            #pragma unroll
            for (int j = k >> 1; j >= 1; j >>= 1) {
                a  = ce_shfl(a,  j, dA, lane);
                bb = ce_shfl(bb, j, dB, lane);
            }
        }
        {   // k = 64: j=32 in-register, then shfl. No smem, no barrier.
            bool dk = ((wid & 1) == 0);
            bool sw = dk ? (a < bb) : (a > bb);
            u64 t0 = sw ? bb : a, t1 = sw ? a : bb;
            a = t0; bb = t1;
            #pragma unroll
            for (int j = 16; j >= 1; j >>= 1) {
                a  = ce_shfl(a,  j, dk, lane);
                bb = ce_shfl(bb, j, dk, lane);
            }
        }
        for (int k = 128; k <= 2048; k <<= 1) {
            sm.cand[e0]      = a;
            sm.cand[e0 + 32] = bb;
            __syncthreads();
            for (int j = k >> 1; j >= 64; j >>= 1) {
                int i   = ((tid & ~(j - 1)) << 1) | (tid & (j - 1));
                int ixj = i | j;
                bool desc = ((i & k) == 0);
                u64 x = sm.cand[i];
                u64 y = sm.cand[ixj];
                u64 mx = x > y ? x : y;
                u64 mn = x > y ? y : x;
                sm.cand[i]   = desc ? mx : mn;   // branch-free: always store
                sm.cand[ixj] = desc ? mn : mx;
                __syncthreads();
            }
            a  = sm.cand[e0];
            bb = sm.cand[e0 + 32];
            bool dk = ((e0 & k) == 0);
            bool sw = dk ? (a < bb) : (a > bb);
            u64 t0 = sw ? bb : a, t1 = sw ? a : bb;
            a = t0; bb = t1;
            #pragma unroll
            for (int j = 16; j >= 1; j >>= 1) {
                a  = ce_shfl(a,  j, dk, lane);
                bb = ce_shfl(bb, j, dk, lane);
            }
        }
        // thread holds rank e0 in `a`, rank e0+32 in `bb`: emit directly
        // (no redistribute barrier, no smem round-trip).
        if (e0 < KTOP)
            emit_row(b, e0, a, bb0, bb1, bb2, out_boxes, out_scores);
        if (e0 + 32 < KTOP)
            emit_row(b, e0 + 32, bb, bb0, bb1, bb2, out_boxes, out_scores);
    } else {
        // ---- generic smem bitonic, P=4096 (rare) ----
        for (int k = 2; k <= 4096; k <<= 1) {
            for (int j = k >> 1; j > 0; j >>= 1) {
                for (int i = tid; i < 4096; i += THREADS) {
                    int ixj = i ^ j;
                    if (ixj > i) {
                        u64 x = sm.cand[i];
                        u64 y = sm.cand[ixj];
                        bool desc = ((i & k) == 0);
                        if (desc ? (x < y) : (x > y)) {
                            sm.cand[i] = y;
                            sm.cand[ixj] = x;
                        }
                    }
                }
                __syncthreads();
            }
        }
        if (tid < KTOP)
            emit_row(b, tid, sm.cand[tid], bb0, bb1, bb2, out_boxes, out_scores);
    }
}

extern "C" void kernel_launch(void* const* d_in, const int* in_sizes, int n_in,
                              void* d_out, int out_size)
{
    const float *cls0, *cls1, *cls2, *b0, *b1, *b2;

    const int S_CLS0 = BATCH * N0;      // 3276800
    const int S_BB0  = BATCH * 4 * N0;  // 13107200

    if (n_in >= 6 && in_sizes[0] == S_CLS0 && in_sizes[1] == S_BB0) {
        // dict-insertion order: cls0, bbox0, cls1, bbox1, cls2, bbox2
        cls0 = (const float*)d_in[0]; b0 = (const float*)d_in[1];
        cls1 = (const float*)d_in[2]; b1 = (const float*)d_in[3];
        cls2 = (const float*)d_in[4]; b2 = (const float*)d_in[5];
    } else if (n_in >= 6 && in_sizes[0] == S_BB0) {
        // alphabetical order: bbox0, bbox1, bbox2, cls0, cls1, cls2
        b0   = (const float*)d_in[0]; b1   = (const float*)d_in[1];
        b2   = (const float*)d_in[2]; cls0 = (const float*)d_in[3];
        cls1 = (const float*)d_in[4]; cls2 = (const float*)d_in[5];
    } else {
        // signature order: cls0, cls1, cls2, bbox0, bbox1, bbox2
        cls0 = (const float*)d_in[0]; cls1 = (const float*)d_in[1];
        cls2 = (const float*)d_in[2]; b0   = (const float*)d_in[3];
        b1   = (const float*)d_in[4]; b2   = (const float*)d_in[5];
    }
    (void)in_sizes; (void)out_size;

    cudaFuncSetAttribute(topk_decode_kernel,
                         cudaFuncAttributeMaxDynamicSharedMemorySize,
                         (int)sizeof(Smem));

    topk_decode_kernel<<<BATCH, THREADS, sizeof(Smem)>>>(
        cls0, cls1, cls2, b0, b1, b2, (float*)d_out);
}